// round 16
// baseline (speedup 1.0000x reference)
#include <cuda_runtime.h>
#include <cuda_fp16.h>
#include <cstdint>

#define BBATCH 8
#define SSEQ   1024
#define DMODEL 768
#define NHEAD  12
#define DHEAD  64
#define MROWS  (BBATCH*SSEQ)     // 8192
#define NBH    (BBATCH*NHEAD)    // 96
#define WSC    32.0f
#define WSCI   0.03125f

// ---------------- scratch (device globals; no allocations allowed) ----------
__device__ float g_attn[(size_t)NBH*SSEQ*SSEQ];          // fallback attn (fp32)
__device__ float g_l[(size_t)NBH*SSEQ];                  // softmax denominators
__device__ __half g_pt  [(size_t)NBH*SSEQ*SSEQ];         // unnormalized exp(S), fp16
__device__ __half g_xh  [(size_t)MROWS*DMODEL];          // x hi
__device__ __half g_wqkvh[(size_t)3*DMODEL*DMODEL];      // Wq|Wk|Wv rows, hi (x32)
__device__ __half g_woh [(size_t)DMODEL*DMODEL];         // Wo hi (x32)
__device__ __half g_q  [(size_t)NBH*SSEQ*DHEAD];         // q*0.125 single fp16
__device__ __half g_k  [(size_t)NBH*SSEQ*DHEAD];         // k single fp16
__device__ __half g_v  [(size_t)NBH*SSEQ*DHEAD];         // V single fp16
__device__ __half g_ch [(size_t)MROWS*DMODEL];           // ctx single fp16

// ============================ PTX helpers ===================================
__device__ __forceinline__ uint32_t smem_u32(const void* p) {
    uint32_t a;
    asm("{ .reg .u64 t; cvta.to.shared.u64 t, %1; cvt.u32.u64 %0, t; }" : "=r"(a) : "l"(p));
    return a;
}
#define SWZ(o) ((uint32_t)(o) ^ ((((uint32_t)(o)) >> 3) & 0x70))

__device__ __forceinline__ void cp16(uint32_t s, const void* g) {
    asm volatile("cp.async.cg.shared.global [%0], [%1], 16;" :: "r"(s), "l"(g));
}
#define CP_COMMIT() asm volatile("cp.async.commit_group;")
#define CP_WAIT(n)  asm volatile("cp.async.wait_group %0;" :: "n"(n))

__device__ __forceinline__ void ldsm4(uint32_t& r0, uint32_t& r1, uint32_t& r2, uint32_t& r3, uint32_t a) {
    asm volatile("ldmatrix.sync.aligned.m8n8.x4.shared.b16 {%0,%1,%2,%3}, [%4];"
                 : "=r"(r0), "=r"(r1), "=r"(r2), "=r"(r3) : "r"(a));
}
__device__ __forceinline__ void ldsm4t(uint32_t& r0, uint32_t& r1, uint32_t& r2, uint32_t& r3, uint32_t a) {
    asm volatile("ldmatrix.sync.aligned.m8n8.x4.trans.shared.b16 {%0,%1,%2,%3}, [%4];"
                 : "=r"(r0), "=r"(r1), "=r"(r2), "=r"(r3) : "r"(a));
}
__device__ __forceinline__ void mma16816(float* c, const uint32_t* a, const uint32_t* b) {
    asm volatile("mma.sync.aligned.m16n8k16.row.col.f32.f16.f16.f32 "
                 "{%0,%1,%2,%3}, {%4,%5,%6,%7}, {%8,%9}, {%0,%1,%2,%3};"
                 : "+f"(c[0]), "+f"(c[1]), "+f"(c[2]), "+f"(c[3])
                 : "r"(a[0]), "r"(a[1]), "r"(a[2]), "r"(a[3]), "r"(b[0]), "r"(b[1]));
}

__device__ __forceinline__ uint32_t pk_hi(float x, float y) {
    __half2 t; t.x = __float2half_rn(x); t.y = __float2half_rn(y);
    return *(uint32_t*)&t;
}

// ============================ unified GEMM (HMMA fp16, 3-stage) =============
// mode 0: QKV merged (N=2304, K=768; sel 0=q(*0.125)/1=k/2=v, single fp16)
// mode 1: final (N=768, K=768, 1-term ctx; fp32 out + bias)
// row_base: offset into A rows (for batch-split launches)
__global__ __launch_bounds__(256, 2) void hgemm(
    const __half* __restrict__ Ag, const __half* __restrict__ Bg,
    const float* __restrict__ b0p, const float* __restrict__ b1p, const float* __restrict__ b2p,
    void* __restrict__ o0, void* __restrict__ o1, void* __restrict__ o2,
    int K, int ldA, int ldB, int mode, int row_base)
{
    constexpr int BM = 128, BN = 128, BK = 64;
    constexpr int MI = 4, NI = 4;
    constexpr int SA = BM * BK * 2, SB = BN * BK * 2, STG = SA + SB;  // 32KB/stage

    extern __shared__ char smem[];
    const uint32_t sbase = smem_u32(smem);
    const int tid = threadIdx.x, l = tid & 31, wid = tid >> 5;
    const int row0 = row_base + blockIdx.y * BM, col0 = blockIdx.x * BN;
    const int wm0 = (wid / 4) * 64, wn0 = (wid % 4) * 32;

    auto issue = [&](int ch, int st) {
        const int k0 = ch * BK;
        const uint32_t sA = sbase + st * STG;
        const uint32_t sB = sA + SA;
        for (int i = tid; i < BM * 8; i += 256) {
            int r = i >> 3, v = i & 7;
            cp16(sA + SWZ(r * 128 + v * 16), Ag + (size_t)(row0 + r) * ldA + k0 + v * 8);
        }
        for (int i = tid; i < BN * 8; i += 256) {
            int r = i >> 3, v = i & 7;
            cp16(sB + SWZ(r * 128 + v * 16), Bg + (size_t)(col0 + r) * ldB + k0 + v * 8);
        }
    };

    float c[MI][NI][4] = {};
    const int nch = K / BK;
    issue(0, 0); CP_COMMIT();
    if (nch > 1) { issue(1, 1); CP_COMMIT(); }

    for (int ch = 0; ch < nch; ch++) {
        if (ch + 1 < nch) { CP_WAIT(1); } else { CP_WAIT(0); }
        __syncthreads();
        if (ch + 2 < nch) { issue(ch + 2, (ch + 2) % 3); CP_COMMIT(); }

        const uint32_t sA = sbase + (ch % 3) * STG;
        const uint32_t sB = sA + SA;

        #pragma unroll
        for (int ks = 0; ks < 4; ks++) {
            uint32_t af[MI][4];
            #pragma unroll
            for (int im = 0; im < MI; im++)
                ldsm4(af[im][0], af[im][1], af[im][2], af[im][3],
                      sA + SWZ((wm0 + im * 16 + (l & 15)) * 128 + ks * 32 + ((l >> 4) & 1) * 16));
            uint32_t bf[NI][2];
            #pragma unroll
            for (int i2 = 0; i2 < NI / 2; i2++) {
                int g = l >> 3;
                uint32_t r0, r1, r2, r3;
                ldsm4(r0, r1, r2, r3,
                      sB + SWZ((wn0 + i2 * 16 + ((g >> 1) & 1) * 8 + (l & 7)) * 128 + ks * 32 + (g & 1) * 16));
                bf[2 * i2][0] = r0; bf[2 * i2][1] = r1;
                bf[2 * i2 + 1][0] = r2; bf[2 * i2 + 1][1] = r3;
            }
            #pragma unroll
            for (int im = 0; im < MI; im++)
                #pragma unroll
                for (int in = 0; in < NI; in++)
                    mma16816(c[im][in], af[im], bf[in]);
        }
    }
    __syncthreads();

    const int sel = (mode == 0) ? col0 / DMODEL : 3;          // 0 q, 1 k, 2 v, 3 final
    const int dcol0 = col0 % DMODEL;
    const float* bs = (sel == 1) ? b1p : (sel == 2) ? b2p : b0p;
    const float qsc = (sel == 0) ? 0.125f : 1.0f;

    #pragma unroll
    for (int im = 0; im < MI; im++)
        #pragma unroll
        for (int in = 0; in < NI; in++)
            #pragma unroll
            for (int half_ = 0; half_ < 2; half_++) {
                int m = row0 + wm0 + im * 16 + (l >> 2) + half_ * 8;
                int nd = dcol0 + wn0 + in * 8 + (l & 3) * 2;
                float v0 = c[im][in][2 * half_] * WSCI + bs[nd];
                float v1 = c[im][in][2 * half_ + 1] * WSCI + bs[nd + 1];
                if (sel == 3) {
                    float2 w; w.x = v0; w.y = v1;
                    *(float2*)((float*)o0 + (size_t)m * DMODEL + nd) = w;
                    continue;
                }
                v0 *= qsc; v1 *= qsc;
                int b = m >> 10, s = m & 1023, h = nd >> 6, dd = nd & 63;
                __half2 t; t.x = __float2half_rn(v0); t.y = __float2half_rn(v1);
                __half* ob = (sel == 0) ? (__half*)o0 : (sel == 1) ? (__half*)o1 : (__half*)o2;
                *(__half2*)(ob + ((size_t)(b * NHEAD + h) * SSEQ + s) * DHEAD + dd) = t;
            }
}

// ============================ fused attention ===============================
// CTA: (bh_base + blockIdx.y, 64 q-rows). 8 warps: rg rows, ch kv half.
#define SQ_OFF  0                         // 8KB q
#define SK_OFF  8192                      // 2 x 16KB K buffers
#define SV_OFF  40960                     // 16KB V
#define SRED_O  8192                      // reuse K region post-loop (16KB)
#define SRED_L  (8192 + 16384)
#define FSM_BYTES 57344

__global__ __launch_bounds__(256, 2) void fused_attn(
    const __half* __restrict__ Qp, const __half* __restrict__ Kp,
    const __half* __restrict__ Vp,
    __half* __restrict__ pt, float* __restrict__ lbuf,
    __half* __restrict__ ch_out, int bh_base)
{
    extern __shared__ char smem[];
    const uint32_t sbase = smem_u32(smem);
    const int tid = threadIdx.x, l = tid & 31, wid = tid >> 5;
    const int rg = wid >> 1, ch = wid & 1;
    const int bh = bh_base + blockIdx.y, q0 = blockIdx.x * 64;
    const int wm0 = rg * 16;

    const __half* Qb = Qp + (size_t)bh * SSEQ * DHEAD;
    const __half* Kb = Kp + (size_t)bh * SSEQ * DHEAD;
    const __half* Vb = Vp + (size_t)bh * SSEQ * DHEAD;

    auto issueK = [&](int t, int st) {
        const uint32_t kb = sbase + SK_OFF + st * 16384;
        for (int i = tid; i < 1024; i += 256) {
            int r = i >> 3, v = i & 7;
            cp16(kb + SWZ(r * 128 + v * 16), Kb + (size_t)(t * 128 + r) * DHEAD + v * 8);
        }
    };
    auto issueV = [&](int t) {
        for (int i = tid; i < 1024; i += 256) {
            int r = i >> 3, v = i & 7;
            cp16(sbase + SV_OFF + SWZ(r * 128 + v * 16),
                 Vb + (size_t)(t * 128 + r) * DHEAD + v * 8);
        }
    };

    for (int i = tid; i < 512; i += 256) {
        int r = i >> 3, v = i & 7;
        cp16(sbase + SQ_OFF + SWZ(r * 128 + v * 16), Qb + (size_t)(q0 + r) * DHEAD + v * 8);
    }
    issueK(0, 0);
    CP_COMMIT();

    float c_o[8][4] = {};
    float lsum0 = 0.f, lsum1 = 0.f;

    for (int t = 0; t < 8; t++) {
        CP_WAIT(0);
        __syncthreads();
        issueV(t); CP_COMMIT();
        if (t < 7) { issueK(t + 1, (t + 1) & 1); CP_COMMIT(); }

        // ---- S: 16 q-rows x 64 kv (this warp's half), 1-term ----
        float cs[8][4] = {};
        const uint32_t kb = sbase + SK_OFF + (t & 1) * 16384;
        const uint32_t sQ = sbase + SQ_OFF;
        #pragma unroll
        for (int ks = 0; ks < 4; ks++) {
            uint32_t af[4];
            ldsm4(af[0], af[1], af[2], af[3],
                  sQ + SWZ((wm0 + (l & 15)) * 128 + ks * 32 + ((l >> 4) & 1) * 16));
            #pragma unroll
            for (int i2 = 0; i2 < 4; i2++) {
                int g = l >> 3;
                uint32_t r0, r1, r2, r3;
                ldsm4(r0, r1, r2, r3,
                      kb + SWZ((ch * 64 + i2 * 16 + ((g >> 1) & 1) * 8 + (l & 7)) * 128
                               + ks * 32 + (g & 1) * 16));
                uint32_t b0[2] = {r0, r1}, b1[2] = {r2, r3};
                mma16816(cs[2 * i2],     af, b0);
                mma16816(cs[2 * i2 + 1], af, b1);
            }
        }

        // ---- exp + row-sum; pack P-hi (feeds PV and p~ write) ----
        uint32_t ph[8][2];
        #pragma unroll
        for (int in = 0; in < 8; in++) {
            cs[in][0] = __expf(cs[in][0]);
            cs[in][1] = __expf(cs[in][1]);
            cs[in][2] = __expf(cs[in][2]);
            cs[in][3] = __expf(cs[in][3]);
            lsum0 += cs[in][0] + cs[in][1];
            lsum1 += cs[in][2] + cs[in][3];
            ph[in][0] = pk_hi(cs[in][0], cs[in][1]);
            ph[in][1] = pk_hi(cs[in][2], cs[in][3]);
        }
        {
            __half* p0 = pt + ((size_t)bh << 20) + (size_t)(q0 + wm0 + (l >> 2)) * SSEQ
                         + t * 128 + ch * 64 + 2 * (l & 3);
            __half* p1 = p0 + 8 * SSEQ;
            #pragma unroll
            for (int in = 0; in < 8; in++) {
                *(uint32_t*)(p0 + in * 8) = ph[in][0];
                *(uint32_t*)(p1 + in * 8) = ph[in][1];
            }
        }

        if (t < 7) CP_WAIT(1); else CP_WAIT(0);
        __syncthreads();

        // ---- partial O += P~hi @ V over warp's 64 kv (1-term) ----
        const uint32_t sVh = sbase + SV_OFF;
        #pragma unroll
        for (int kk = 0; kk < 4; kk++) {
            uint32_t ah[4];
            ah[0] = ph[2*kk][0];   ah[1] = ph[2*kk][1];
            ah[2] = ph[2*kk+1][0]; ah[3] = ph[2*kk+1][1];
            uint32_t vrow = (uint32_t)(ch * 64 + kk * 16 + ((l >> 3) & 1) * 8 + (l & 7)) * 128
                          + ((uint32_t)(l >> 4)) * 16;
            #pragma unroll
            for (int in = 0; in < 8; in += 2) {
                uint32_t h0, h1, h2, h3;
                ldsm4t(h0, h1, h2, h3, sVh + SWZ(vrow + in * 16));
                uint32_t bh2[2] = {h0, h1}, bh3[2] = {h2, h3};
                mma16816(c_o[in],     ah, bh2);
                mma16816(c_o[in + 1], ah, bh3);
            }
        }
        __syncthreads();
    }

    // ---- pair reduction (ch=1 -> smem -> ch=0), then finalize ----
    lsum0 += __shfl_xor_sync(0xffffffffu, lsum0, 1);
    lsum0 += __shfl_xor_sync(0xffffffffu, lsum0, 2);
    lsum1 += __shfl_xor_sync(0xffffffffu, lsum1, 1);
    lsum1 += __shfl_xor_sync(0xffffffffu, lsum1, 2);

    float* redO = (float*)(smem + SRED_O);             // 4 rg x 16 x 64 = 16KB
    float* redL = (float*)(smem + SRED_L);             // 4 rg x 16
    __syncthreads();
    if (ch == 1) {
        #pragma unroll
        for (int in = 0; in < 8; in++) {
            int cidx = in * 8 + 2 * (l & 3);
            int r = l >> 2;
            redO[rg * 1024 + r * 64 + cidx]           = c_o[in][0];
            redO[rg * 1024 + r * 64 + cidx + 1]       = c_o[in][1];
            redO[rg * 1024 + (r + 8) * 64 + cidx]     = c_o[in][2];
            redO[rg * 1024 + (r + 8) * 64 + cidx + 1] = c_o[in][3];
        }
        if ((l & 3) == 0) {
            redL[rg * 16 + (l >> 2)]     = lsum0;
            redL[rg * 16 + (l >> 2) + 8] = lsum1;
        }
    }
    __syncthreads();
    if (ch == 0) {
        lsum0 += redL[rg * 16 + (l >> 2)];
        lsum1 += redL[rg * 16 + (l >> 2) + 8];
        const float inv0 = 1.0f / lsum0, inv1 = 1.0f / lsum1;

        const int r0g = q0 + wm0 + (l >> 2);
        if ((l & 3) == 0) {
            lbuf[(size_t)bh * SSEQ + r0g]     = lsum0;
            lbuf[(size_t)bh * SSEQ + r0g + 8] = lsum1;
        }
        const int b = bh / NHEAD, h = bh % NHEAD;
        const size_t gm0 = (size_t)(b * SSEQ + r0g) * DMODEL;
        const size_t gm1 = gm0 + (size_t)8 * DMODEL;
        #pragma unroll
        for (int in = 0; in < 8; in++) {
            int cidx = in * 8 + 2 * (l & 3);
            int r = l >> 2;
            float o0 = (c_o[in][0] + redO[rg * 1024 + r * 64 + cidx])           * inv0;
            float o1 = (c_o[in][1] + redO[rg * 1024 + r * 64 + cidx + 1])       * inv0;
            float o2 = (c_o[in][2] + redO[rg * 1024 + (r + 8) * 64 + cidx])     * inv1;
            float o3 = (c_o[in][3] + redO[rg * 1024 + (r + 8) * 64 + cidx + 1]) * inv1;
            int d = h * DHEAD + cidx;
            __half2 t0; t0.x = __float2half_rn(o0); t0.y = __float2half_rn(o1);
            __half2 t1; t1.x = __float2half_rn(o2); t1.y = __float2half_rn(o3);
            *(__half2*)(ch_out + gm0 + d) = t0;
            *(__half2*)(ch_out + gm1 + d) = t1;
        }
    }
}

// rescale: 2 rows/block, 16B p~ loads, 32B fp32 stores; row_base selects half
__global__ __launch_bounds__(256) void rescale_attn(const __half* __restrict__ pt,
                                                    float* __restrict__ attn,
                                                    const float* __restrict__ lbuf,
                                                    size_t row_base)
{
    const int t = threadIdx.x;
    const size_t row = row_base + (size_t)blockIdx.x * 2 + (t >> 7);
    const int lane = t & 127;
    const float inv = 1.0f / lbuf[row];
    const uint4* s = (const uint4*)(pt + row * SSEQ);
    float4* d = (float4*)(attn + row * SSEQ);
    uint4 pv = s[lane];
    __half2 h0 = *(__half2*)&pv.x, h1 = *(__half2*)&pv.y;
    __half2 h2 = *(__half2*)&pv.z, h3 = *(__half2*)&pv.w;
    float4 v0, v1;
    v0.x = __half2float(h0.x) * inv; v0.y = __half2float(h0.y) * inv;
    v0.z = __half2float(h1.x) * inv; v0.w = __half2float(h1.y) * inv;
    v1.x = __half2float(h2.x) * inv; v1.y = __half2float(h2.y) * inv;
    v1.z = __half2float(h3.x) * inv; v1.w = __half2float(h3.y) * inv;
    d[2 * lane]     = v0;
    d[2 * lane + 1] = v1;
}

// ============================ prep kernels ==================================
__global__ __launch_bounds__(256) void pack_x(const float* __restrict__ in, __half* __restrict__ o)
{
    size_t i = (size_t)blockIdx.x * 256 + threadIdx.x;   // float4 index
    if (i >= (size_t)MROWS * DMODEL / 4) return;
    float4 v = ((const float4*)in)[i];
    __half2 a, b;
    a.x = __float2half_rn(v.x); a.y = __float2half_rn(v.y);
    b.x = __float2half_rn(v.z); b.y = __float2half_rn(v.w);
    ((__half2*)o)[2 * i]     = a;
    ((__half2*)o)[2 * i + 1] = b;
}

__global__ void pack_w_all(const float* __restrict__ Wq, const float* __restrict__ Wk,
                           const float* __restrict__ Wv, const float* __restrict__ Wo,
                           __half* __restrict__ wqkvh, __half* __restrict__ woh)
{
    __shared__ float t[32][33];
    const int z = blockIdx.z;
    const float* W = (z == 0) ? Wq : (z == 1) ? Wk : (z == 2) ? Wv : Wo;
    int n0 = blockIdx.x * 32, k0 = blockIdx.y * 32;
    int x = threadIdx.x, y = threadIdx.y;
    #pragma unroll
    for (int j = 0; j < 32; j += 8)
        t[y + j][x] = W[(size_t)(k0 + y + j) * DMODEL + n0 + x] * WSC;
    __syncthreads();
    __half* o = (z == 3) ? woh : wqkvh + (size_t)z * DMODEL * DMODEL;
    #pragma unroll
    for (int j = 0; j < 32; j += 8)
        o[(size_t)(n0 + y + j) * DMODEL + k0 + x] = __float2half_rn(t[x][y + j]);
}

// ============================ host launcher =================================
extern "C" void kernel_launch(void* const* d_in, const int* in_sizes, int n_in,
                              void* d_out, int out_size)
{
    (void)in_sizes; (void)n_in;
    const float* x  = (const float*)d_in[0];
    const float* Wq = (const float*)d_in[1];
    const float* bq = (const float*)d_in[2];
    const float* Wk = (const float*)d_in[3];
    const float* bk = (const float*)d_in[4];
    const float* Wv = (const float*)d_in[5];
    const float* bv = (const float*)d_in[6];
    const float* Wo = (const float*)d_in[7];
    const float* bo = (const float*)d_in[8];
    float* out = (float*)d_out;

    float *gattn, *gl;
    __half *pt, *xh, *wqkvh, *woh, *qP, *kP, *vP, *chx;
    cudaGetSymbolAddress((void**)&gattn, g_attn);
    cudaGetSymbolAddress((void**)&gl,    g_l);
    cudaGetSymbolAddress((void**)&pt,    g_pt);
    cudaGetSymbolAddress((void**)&xh,    g_xh);
    cudaGetSymbolAddress((void**)&wqkvh, g_wqkvh);
    cudaGetSymbolAddress((void**)&woh,   g_woh);
    cudaGetSymbolAddress((void**)&qP,    g_q);
    cudaGetSymbolAddress((void**)&kP,    g_k);
    cudaGetSymbolAddress((void**)&vP,    g_v);
    cudaGetSymbolAddress((void**)&chx,   g_ch);

    const size_t final_elems = (size_t)MROWS * DMODEL;
    const int wattn = ((size_t)out_size > final_elems) ? 1 : 0;
    float* attn = wattn ? (out + final_elems) : gattn;

    static cudaStream_t s2 = nullptr;
    static cudaEvent_t evF = nullptr, evX = nullptr, evP = nullptr;
    static cudaEvent_t evQ2 = nullptr, evA = nullptr, evB = nullptr, evC = nullptr;
    if (s2 == nullptr) {
        cudaStreamCreateWithFlags(&s2, cudaStreamNonBlocking);
        cudaEventCreateWithFlags(&evF, cudaEventDisableTiming);
        cudaEventCreateWithFlags(&evX, cudaEventDisableTiming);
        cudaEventCreateWithFlags(&evP, cudaEventDisableTiming);
        cudaEventCreateWithFlags(&evQ2, cudaEventDisableTiming);
        cudaEventCreateWithFlags(&evA, cudaEventDisableTiming);
        cudaEventCreateWithFlags(&evB, cudaEventDisableTiming);
        cudaEventCreateWithFlags(&evC, cudaEventDisableTiming);
    }

    constexpr int SM_GEMM = 3 * (128 * 64 * 2 + 128 * 64 * 2);   // 96KB, 3-stage
    cudaFuncSetAttribute(hgemm,      cudaFuncAttributeMaxDynamicSharedMemorySize, SM_GEMM);
    cudaFuncSetAttribute(fused_attn, cudaFuncAttributeMaxDynamicSharedMemorySize, FSM_BYTES);

    // fork s2 from origin (capture-legal), then pack_x(s0) ∥ pack_w(s2)
    cudaEventRecord(evF, 0);
    cudaStreamWaitEvent(s2, evF, 0);
    {
        size_t n4 = (size_t)MROWS * DMODEL / 4;
        pack_x<<<(unsigned)((n4 + 255) / 256), 256>>>(x, xh);
        cudaEventRecord(evX, 0);
        dim3 tb(32, 8), tg(DMODEL / 32, DMODEL / 32, 4);
        pack_w_all<<<tg, tb, 0, s2>>>(Wq, Wk, Wv, Wo, wqkvh, woh);
        cudaEventRecord(evP, s2);
        cudaStreamWaitEvent(0, evP, 0);        // s0 has both packs before qkv1
    }

    // QKV projection split into two batch-halves
    dim3 gqkvh(3 * DMODEL / 128, MROWS / 256);    // (18, 32) per half
    // half 1 (token rows 0..4095) on s0
    hgemm<<<gqkvh, 256, SM_GEMM>>>(xh, wqkvh, bq, bk, bv, qP, kP, vP,
                                   DMODEL, DMODEL, DMODEL, 0, 0);
    // half 2 (rows 4096..8191) on s2, concurrent with fused1
    cudaStreamWaitEvent(s2, evX, 0);              // s2 needs pack_x too
    hgemm<<<gqkvh, 256, SM_GEMM, s2>>>(xh, wqkvh, bq, bk, bv, qP, kP, vP,
                                       DMODEL, DMODEL, DMODEL, 0, MROWS / 2);
    cudaEventRecord(evQ2, s2);

    // fused attention: two bh-halves; fused1 (b<4) needs only qkv half 1
    dim3 gf(SSEQ / 64, NBH / 2);                  // (16, 48)
    fused_attn<<<gf, 256, FSM_BYTES>>>(qP, kP, vP, pt, gl, chx, 0);
    cudaEventRecord(evA, 0);
    cudaStreamWaitEvent(0, evQ2, 0);              // fused2 needs qkv half 2
    fused_attn<<<gf, 256, FSM_BYTES>>>(qP, kP, vP, pt, gl, chx, NBH / 2);
    cudaEventRecord(evB, 0);

    if (wattn) {
        cudaStreamWaitEvent(s2, evA, 0);
        rescale_attn<<<NBH * SSEQ / 4, 256, 0, s2>>>(pt, attn, gl, 0);
        cudaStreamWaitEvent(s2, evB, 0);
        rescale_attn<<<NBH * SSEQ / 4, 256, 0, s2>>>(pt, attn, gl, (size_t)(NBH / 2) * SSEQ);
        cudaEventRecord(evC, s2);
    }

    // out = ctx @ Wo + bo (K = 768, 1-term) — overlaps rescale2 on s2
    dim3 gfin(DMODEL / 128, MROWS / 128);         // (6, 64)
    hgemm<<<gfin, 256, SM_GEMM>>>(chx, woh, bo, nullptr, nullptr, out, nullptr, nullptr,
                                  DMODEL, DMODEL, DMODEL, 1, 0);

    if (wattn) cudaStreamWaitEvent(0, evC, 0);
}